// round 1
// baseline (speedup 1.0000x reference)
#include <cuda_runtime.h>

// Problem constants
#define S   8
#define NCH 7
#define PIX 409600           // 640*640
#define LAMBDA 0.7f
#define EPSV 1e-6f

// ---------------- device scratch (no allocations allowed) ----------------
__device__ float    g_predn[S * PIX];     // sigmoid(pred[:,6]) * mask
__device__ int      g_npos[S];
__device__ unsigned g_hist[S][256];
__device__ unsigned g_prefix[S];
__device__ int      g_krem[S];
__device__ int      g_active[S];
__device__ float    g_thr[S];
__device__ float    g_acc[S][21];         // [0..2]=Lc triple, [3+3c..]=Ls triples

__device__ __forceinline__ float sigmoidf(float x) {
    return 1.f / (1.f + __expf(-x));
}

// ---------------- init: zero all cross-launch state ----------------
__global__ void k_init() {
    int t = blockIdx.x * blockDim.x + threadIdx.x;
    if (t < S * 256) ((unsigned*)g_hist)[t] = 0u;
    if (t < S * 21)  ((float*)g_acc)[t] = 0.f;
    if (t < S)       g_npos[t] = 0;
}

// ---------------- pass 1: pred_n + positive counts ----------------
__global__ void k_predn(const float* __restrict__ preds,
                        const int*   __restrict__ mask) {
    int s = blockIdx.y;
    int i = (blockIdx.x * blockDim.x + threadIdx.x) * 4;
    const float4 x = *(const float4*)(preds + ((size_t)s * NCH + 6) * PIX + i);
    const int4   m = *(const int4*)(mask + (size_t)s * PIX + i);
    float4 pn;
    pn.x = sigmoidf(x.x) * (float)m.x;
    pn.y = sigmoidf(x.y) * (float)m.y;
    pn.z = sigmoidf(x.z) * (float)m.z;
    pn.w = sigmoidf(x.w) * (float)m.w;
    *(float4*)(g_predn + (size_t)s * PIX + i) = pn;
    int cnt = (pn.x >= 0.5f) + (pn.y >= 0.5f) + (pn.z >= 0.5f) + (pn.w >= 0.5f);
    #pragma unroll
    for (int o = 16; o; o >>= 1) cnt += __shfl_down_sync(0xffffffffu, cnt, o);
    if ((threadIdx.x & 31) == 0 && cnt) atomicAdd(&g_npos[s], cnt);
}

// ---------------- OHEM setup ----------------
__global__ void k_setup() {
    int s = threadIdx.x;
    if (s < S) {
        int np = g_npos[s];
        int k = np * 3;
        int nneg = PIX - np;
        g_active[s] = (nneg > k) && (k > 0);
        g_krem[s]   = k;
        g_prefix[s] = 0u;
        g_thr[s]    = 0.f;
    }
}

// ---------------- radix-select histogram pass ----------------
// Negative scores are floats in [0,0.5): non-negative, so raw-bit order == value order.
template <int SHIFT>
__global__ void k_hist() {
    int s = blockIdx.y;
    if (!g_active[s]) return;
    __shared__ unsigned sh[256];
    sh[threadIdx.x] = 0u;
    __syncthreads();
    unsigned pref = g_prefix[s];
    int i = (blockIdx.x * blockDim.x + threadIdx.x) * 4;
    float4 v = *(const float4*)(g_predn + (size_t)s * PIX + i);
    float vv[4] = {v.x, v.y, v.z, v.w};
    #pragma unroll
    for (int j = 0; j < 4; j++) {
        if (vv[j] < 0.5f) {   // negative candidate
            unsigned b = __float_as_uint(vv[j]);
            // 64-bit shift: at pass 0 (SHIFT=24) this is b>>32 == 0 == prefix(0)
            if ((unsigned)((unsigned long long)b >> (SHIFT + 8)) == pref)
                atomicAdd(&sh[(b >> SHIFT) & 255u], 1u);
        }
    }
    __syncthreads();
    unsigned c = sh[threadIdx.x];
    if (c) atomicAdd(&g_hist[s][threadIdx.x], c);
}

// ---------------- radix-select digit pick (one block per sample) ----------------
template <int SHIFT>
__global__ void k_select() {
    int s = blockIdx.x;
    int tid = threadIdx.x;
    if (!g_active[s]) { g_hist[s][tid] = 0u; return; }
    __shared__ unsigned suf[256];
    unsigned h = g_hist[s][tid];
    g_hist[s][tid] = 0u;            // reset for next pass
    suf[tid] = h;
    __syncthreads();
    // suffix sum: suf[t] = sum_{b>=t} hist[b]
    #pragma unroll
    for (int off = 1; off < 256; off <<= 1) {
        unsigned add = (tid + off < 256) ? suf[tid + off] : 0u;
        __syncthreads();
        suf[tid] += add;
        __syncthreads();
    }
    unsigned krem = (unsigned)g_krem[s];
    unsigned mysuf  = suf[tid];
    unsigned nxtsuf = (tid < 255) ? suf[tid + 1] : 0u;
    if (mysuf >= krem && nxtsuf < krem) {   // exactly one thread (suf non-increasing)
        g_krem[s] = (int)(krem - nxtsuf);
        unsigned pref = (g_prefix[s] << 8) | (unsigned)tid;
        g_prefix[s] = pref;
        if (SHIFT == 0) g_thr[s] = __uint_as_float(pref);
    }
}

// ---------------- fused dice reductions ----------------
__global__ void k_reduce(const float* __restrict__ preds,
                         const int*   __restrict__ labels,
                         const int*   __restrict__ mask) {
    int s = blockIdx.y;
    int tid = threadIdx.x;
    int i = (blockIdx.x * blockDim.x + tid) * 4;
    bool  act = g_active[s] != 0;
    float thr = g_thr[s];
    size_t sbase = (size_t)s * NCH * PIX;

    float4 pn4 = *(const float4*)(g_predn + (size_t)s * PIX + i);
    int4   m4  = *(const int4*)(mask + (size_t)s * PIX + i);
    int4   l64 = *(const int4*)(labels + sbase + (size_t)6 * PIX + i);
    float pn[4] = {pn4.x, pn4.y, pn4.z, pn4.w};
    int   mm[4] = {m4.x, m4.y, m4.z, m4.w};
    int   l6[4] = {l64.x, l64.y, l64.z, l64.w};

    float acc[21];
    #pragma unroll
    for (int t = 0; t < 21; t++) acc[t] = 0.f;

    float W[4];
    #pragma unroll
    for (int j = 0; j < 4; j++) {
        float M = act ? (pn[j] >= thr ? 1.f : 0.f) : 1.f;
        W[j] = (pn[j] >= 0.5f) ? 1.f : 0.f;
        float ln = (float)(l6[j] * mm[j]);
        acc[0] += pn[j] * ln * M;
        acc[1] += pn[j] * pn[j] * M;
        acc[2] += ln * M;
    }
    #pragma unroll
    for (int c = 0; c < 6; c++) {
        float4 x4 = *(const float4*)(preds + sbase + (size_t)c * PIX + i);
        int4   lc4 = *(const int4*)(labels + sbase + (size_t)c * PIX + i);
        float xv[4] = {x4.x, x4.y, x4.z, x4.w};
        int   lv[4] = {lc4.x, lc4.y, lc4.z, lc4.w};
        #pragma unroll
        for (int j = 0; j < 4; j++) {
            float pc = sigmoidf(xv[j]);
            float lf = (float)lv[j];
            float w = W[j];
            acc[3 + 3 * c + 0] += pc * lf * w;
            acc[3 + 3 * c + 1] += pc * pc * w;
            acc[3 + 3 * c + 2] += lf * w;
        }
    }

    // block reduce 21 accumulators: warp shuffle -> shared -> atomic
    __shared__ float sh[8][21];
    int lane = tid & 31, warp = tid >> 5;
    #pragma unroll
    for (int t = 0; t < 21; t++) {
        float v = acc[t];
        #pragma unroll
        for (int o = 16; o; o >>= 1) v += __shfl_down_sync(0xffffffffu, v, o);
        if (lane == 0) sh[warp][t] = v;
    }
    __syncthreads();
    if (tid < 21) {
        float v = 0.f;
        #pragma unroll
        for (int w = 0; w < 8; w++) v += sh[w][tid];
        atomicAdd(&g_acc[s][tid], v);
    }
}

// ---------------- final scalar composition ----------------
__global__ void k_final(float* __restrict__ out) {
    if (threadIdx.x != 0 || blockIdx.x != 0) return;
    float Lc_s = 0.f, Ls_s = 0.f, loss_s = 0.f;
    for (int s = 0; s < S; s++) {
        float a0 = g_acc[s][0], a1 = g_acc[s][1], a2 = g_acc[s][2];
        float Lc = 1.f - (2.f * a0) / (a1 + a2 + EPSV);
        float d = 0.f;
        for (int c = 0; c < 6; c++) {
            float b0 = g_acc[s][3 + 3 * c + 0];
            float b1 = g_acc[s][3 + 3 * c + 1];
            float b2 = g_acc[s][3 + 3 * c + 2];
            d += (2.f * b0) / (b1 + b2 + EPSV);
        }
        float Ls = 1.f - d / 6.f;
        Lc_s += Lc;
        Ls_s += Ls;
        loss_s += LAMBDA * Lc + (1.f - LAMBDA) * Ls;
    }
    out[0] = Lc_s / (float)S;
    out[1] = Ls_s / (float)S;
    out[2] = loss_s / (float)S;
}

// ---------------- launch ----------------
extern "C" void kernel_launch(void* const* d_in, const int* in_sizes, int n_in,
                              void* d_out, int out_size) {
    const float* preds  = (const float*)d_in[0];
    const int*   labels = (const int*)d_in[1];
    const int*   mask   = (const int*)d_in[2];
    float* out = (float*)d_out;

    const int TB = 256;
    const int BLK = PIX / (TB * 4);   // 400

    k_init<<<8, TB>>>();
    k_predn<<<dim3(BLK, S), TB>>>(preds, mask);
    k_setup<<<1, 32>>>();

    k_hist<24><<<dim3(BLK, S), TB>>>();  k_select<24><<<S, TB>>>();
    k_hist<16><<<dim3(BLK, S), TB>>>();  k_select<16><<<S, TB>>>();
    k_hist<8><<<dim3(BLK, S), TB>>>();   k_select<8><<<S, TB>>>();
    k_hist<0><<<dim3(BLK, S), TB>>>();   k_select<0><<<S, TB>>>();

    k_reduce<<<dim3(BLK, S), TB>>>(preds, labels, mask);
    k_final<<<1, 32>>>(out);
    (void)in_sizes; (void)n_in; (void)out_size;
}

// round 2
// speedup vs baseline: 1.0392x; 1.0392x over previous
#include <cuda_runtime.h>

// Problem constants
#define S   8
#define NCH 7
#define PIX 409600           // 640*640
#define LAMBDA 0.7f
#define EPSV 1e-6f
#define NBIN 1024            // 10-bit radix digits; key is 30 bits (value in [0,0.5))

// ---------------- device scratch (zero-initialized at module load; every
// kernel restores the zero/overwritten invariant so no init pass is needed) --
__device__ float    g_predn[S * PIX];     // sigmoid(pred[:,6]) * mask
__device__ int      g_npos[S];
__device__ unsigned g_hist[S][NBIN];
__device__ unsigned g_prefix[S];
__device__ int      g_krem[S];
__device__ int      g_active[S];
__device__ float    g_thr[S];
__device__ float    g_acc[S][21];         // [0..2]=Lc triple, [3+3c..]=Ls triples
__device__ unsigned g_counter;

__device__ __forceinline__ float sigmoidf(float x) {
    return 1.f / (1.f + __expf(-x));
}

// Warp-dedup'd shared histogram add: one atomic per distinct bin per warp.
__device__ __forceinline__ void hist_add(unsigned* sh, bool participate, unsigned bin) {
    unsigned ballot = __ballot_sync(0xffffffffu, participate);
    if (participate) {
        unsigned grp = __match_any_sync(ballot, bin);
        int leader = __ffs(grp) - 1;
        if ((int)(threadIdx.x & 31) == leader)
            atomicAdd(&sh[bin], (unsigned)__popc(grp));
    }
}

// ---------------- pass 1: pred_n + positive counts + radix pass-0 hist ------
__global__ void k_predn(const float* __restrict__ preds,
                        const int*   __restrict__ mask) {
    __shared__ unsigned sh[NBIN];
    int tid = threadIdx.x;
    #pragma unroll
    for (int b = tid; b < NBIN; b += 256) sh[b] = 0u;
    __syncthreads();

    int s = blockIdx.y;
    int i = (blockIdx.x * blockDim.x + tid) * 4;
    const float4 x = *(const float4*)(preds + ((size_t)s * NCH + 6) * PIX + i);
    const int4   m = *(const int4*)(mask + (size_t)s * PIX + i);
    float pn[4];
    pn[0] = sigmoidf(x.x) * (float)m.x;
    pn[1] = sigmoidf(x.y) * (float)m.y;
    pn[2] = sigmoidf(x.z) * (float)m.z;
    pn[3] = sigmoidf(x.w) * (float)m.w;
    *(float4*)(g_predn + (size_t)s * PIX + i) = make_float4(pn[0], pn[1], pn[2], pn[3]);

    int cnt = 0;
    #pragma unroll
    for (int j = 0; j < 4; j++) {
        bool isneg = pn[j] < 0.5f;
        cnt += !isneg;
        // key = float bits; values in [0,0.5) are non-negative floats -> bit order == value order
        hist_add(sh, isneg, __float_as_uint(pn[j]) >> 20);
    }
    #pragma unroll
    for (int o = 16; o; o >>= 1) cnt += __shfl_down_sync(0xffffffffu, cnt, o);
    if ((tid & 31) == 0 && cnt) atomicAdd(&g_npos[s], cnt);

    __syncthreads();
    #pragma unroll
    for (int b = tid; b < NBIN; b += 256) {
        unsigned c = sh[b];
        if (c) atomicAdd(&g_hist[s][b], c);
    }
}

// ---------------- radix pass histograms (prefix-filtered) -------------------
template <int SHIFT>   // SHIFT=10 (pass1, match key>>20), SHIFT=0 (pass2, match key>>10)
__global__ void k_hist() {
    int s = blockIdx.y;
    if (!g_active[s]) return;
    __shared__ unsigned sh[NBIN];
    int tid = threadIdx.x;
    #pragma unroll
    for (int b = tid; b < NBIN; b += 256) sh[b] = 0u;
    __syncthreads();

    unsigned pref = g_prefix[s];
    int i = (blockIdx.x * blockDim.x + tid) * 4;
    float4 v = *(const float4*)(g_predn + (size_t)s * PIX + i);
    float vv[4] = {v.x, v.y, v.z, v.w};
    #pragma unroll
    for (int j = 0; j < 4; j++) {
        unsigned b = __float_as_uint(vv[j]);
        bool hit = (vv[j] < 0.5f) && ((b >> (SHIFT + 10)) == pref);
        hist_add(sh, hit, (b >> SHIFT) & (NBIN - 1u));
    }
    __syncthreads();
    #pragma unroll
    for (int b = tid; b < NBIN; b += 256) {
        unsigned c = sh[b];
        if (c) atomicAdd(&g_hist[s][b], c);
    }
}

// ---------------- radix digit pick (one 1024-thread block per sample) ------
template <int STAGE>   // 0, 1, 2
__global__ void k_select() {
    int s = blockIdx.x;
    int tid = threadIdx.x;
    __shared__ unsigned suf[NBIN];
    __shared__ int sh_np;

    unsigned h = g_hist[s][tid];
    if (STAGE == 0 && tid == 0) sh_np = g_npos[s];
    __syncthreads();
    g_hist[s][tid] = 0u;            // reset bins for next pass / next replay

    int active;
    unsigned krem;
    if (STAGE == 0) {
        int np = sh_np;
        if (tid == 0) g_npos[s] = 0;      // restore zero invariant for replay
        int k = np * 3;
        active = (PIX - np > k) && (k > 0);
        krem = (unsigned)k;
        if (tid == 0) {
            g_active[s] = active;
            if (!active) g_thr[s] = 0.f;  // deterministic even when OHEM off
        }
    } else {
        active = g_active[s];
        krem = (unsigned)g_krem[s];
    }
    if (!active) return;

    suf[tid] = h;
    __syncthreads();
    // suffix sum: suf[t] = sum_{b>=t} hist[b]
    #pragma unroll
    for (int off = 1; off < NBIN; off <<= 1) {
        unsigned add = (tid + off < NBIN) ? suf[tid + off] : 0u;
        __syncthreads();
        suf[tid] += add;
        __syncthreads();
    }
    unsigned mysuf  = suf[tid];
    unsigned nxtsuf = (tid < NBIN - 1) ? suf[tid + 1] : 0u;
    if (mysuf >= krem && nxtsuf < krem) {   // exactly one thread (suf non-increasing)
        g_krem[s] = (int)(krem - nxtsuf);
        unsigned pref = (STAGE == 0) ? (unsigned)tid
                                     : ((g_prefix[s] << 10) | (unsigned)tid);
        g_prefix[s] = pref;
        if (STAGE == 2) g_thr[s] = __uint_as_float(pref);  // full 30-bit key
    }
}

// ---------------- fused dice reductions + final composition ----------------
__global__ void k_reduce(const float* __restrict__ preds,
                         const int*   __restrict__ labels,
                         const int*   __restrict__ mask,
                         float* __restrict__ out) {
    int s = blockIdx.y;
    int tid = threadIdx.x;
    int i = (blockIdx.x * blockDim.x + tid) * 4;
    bool  act = g_active[s] != 0;
    float thr = g_thr[s];
    size_t sbase = (size_t)s * NCH * PIX;

    float4 pn4 = *(const float4*)(g_predn + (size_t)s * PIX + i);
    int4   m4  = *(const int4*)(mask + (size_t)s * PIX + i);
    int4   l64 = *(const int4*)(labels + sbase + (size_t)6 * PIX + i);
    float pn[4] = {pn4.x, pn4.y, pn4.z, pn4.w};
    int   mm[4] = {m4.x, m4.y, m4.z, m4.w};
    int   l6[4] = {l64.x, l64.y, l64.z, l64.w};

    float acc[21];
    #pragma unroll
    for (int t = 0; t < 21; t++) acc[t] = 0.f;

    float W[4];
    #pragma unroll
    for (int j = 0; j < 4; j++) {
        float M = act ? (pn[j] >= thr ? 1.f : 0.f) : 1.f;
        W[j] = (pn[j] >= 0.5f) ? 1.f : 0.f;
        float ln = (float)(l6[j] * mm[j]);
        acc[0] += pn[j] * ln * M;
        acc[1] += pn[j] * pn[j] * M;
        acc[2] += ln * M;
    }
    #pragma unroll
    for (int c = 0; c < 6; c++) {
        float4 x4  = *(const float4*)(preds  + sbase + (size_t)c * PIX + i);
        int4   lc4 = *(const int4*)(labels + sbase + (size_t)c * PIX + i);
        float xv[4] = {x4.x, x4.y, x4.z, x4.w};
        int   lv[4] = {lc4.x, lc4.y, lc4.z, lc4.w};
        #pragma unroll
        for (int j = 0; j < 4; j++) {
            float pc = sigmoidf(xv[j]);
            float lf = (float)lv[j];
            float w  = W[j];
            acc[3 + 3 * c + 0] += pc * lf * w;
            acc[3 + 3 * c + 1] += pc * pc * w;
            acc[3 + 3 * c + 2] += lf * w;
        }
    }

    // block reduce 21 accumulators: warp shuffle -> shared -> atomic
    __shared__ float sh[8][21];
    __shared__ bool  is_last;
    int lane = tid & 31, warp = tid >> 5;
    #pragma unroll
    for (int t = 0; t < 21; t++) {
        float v = acc[t];
        #pragma unroll
        for (int o = 16; o; o >>= 1) v += __shfl_down_sync(0xffffffffu, v, o);
        if (lane == 0) sh[warp][t] = v;
    }
    __syncthreads();
    if (tid < 21) {
        float v = 0.f;
        #pragma unroll
        for (int w = 0; w < 8; w++) v += sh[w][tid];
        atomicAdd(&g_acc[s][tid], v);
    }

    // last-block-done: compose final scalars, then restore zero invariant
    __threadfence();
    if (tid == 0) {
        unsigned total = gridDim.x * gridDim.y;
        unsigned t = atomicAdd(&g_counter, 1u);
        is_last = (t == total - 1);
    }
    __syncthreads();
    if (is_last && tid == 0) {
        float Lc_s = 0.f, Ls_s = 0.f, loss_s = 0.f;
        for (int ss = 0; ss < S; ss++) {
            float a[21];
            for (int t = 0; t < 21; t++) {
                a[t] = __ldcg(&g_acc[ss][t]);   // L2 read: skip possibly-stale L1
                g_acc[ss][t] = 0.f;
            }
            float Lc = 1.f - (2.f * a[0]) / (a[1] + a[2] + EPSV);
            float d = 0.f;
            for (int c = 0; c < 6; c++)
                d += (2.f * a[3 + 3 * c]) / (a[4 + 3 * c] + a[5 + 3 * c] + EPSV);
            float Ls = 1.f - d / 6.f;
            Lc_s += Lc; Ls_s += Ls;
            loss_s += LAMBDA * Lc + (1.f - LAMBDA) * Ls;
        }
        out[0] = Lc_s / (float)S;
        out[1] = Ls_s / (float)S;
        out[2] = loss_s / (float)S;
        g_counter = 0u;
    }
}

// ---------------- launch ----------------
extern "C" void kernel_launch(void* const* d_in, const int* in_sizes, int n_in,
                              void* d_out, int out_size) {
    const float* preds  = (const float*)d_in[0];
    const int*   labels = (const int*)d_in[1];
    const int*   mask   = (const int*)d_in[2];
    float* out = (float*)d_out;

    const int TB = 256;
    const int BLK = PIX / (TB * 4);   // 400

    k_predn<<<dim3(BLK, S), TB>>>(preds, mask);   // + radix pass-0 hist
    k_select<0><<<S, NBIN>>>();                   // + OHEM setup
    k_hist<10><<<dim3(BLK, S), TB>>>();
    k_select<1><<<S, NBIN>>>();
    k_hist<0><<<dim3(BLK, S), TB>>>();
    k_select<2><<<S, NBIN>>>();                   // writes g_thr
    k_reduce<<<dim3(BLK, S), TB>>>(preds, labels, mask, out);  // + final
    (void)in_sizes; (void)n_in; (void)out_size;
}